// round 1
// baseline (speedup 1.0000x reference)
#include <cuda_runtime.h>
#include <cuda_bf16.h>
#include <math.h>

// Problem constants
#define B_   2
#define S_   2048
#define DIN_ 2048
#define H_   32
#define G_   8
#define D_   64
#define GS_  4
#define M_   (B_*S_)

#define OUT_ELEMS ((size_t)B_*S_*DIN_)      // 8388608
#define KV_ELEMS  ((size_t)B_*G_*S_*D_)     // 2097152

// Scratch (static device arrays: allocation-guard safe)
__device__ float g_Q[(size_t)B_*H_*S_*D_];     // (b,h,s,d), rms+rope+1/sqrt(D) applied
__device__ float g_ctx[(size_t)B_*S_*H_*D_];   // (b,s,h,d)

// ============================================================
// SGEMM: C = A(M,K) @ B(K,N), row-major. 128x128x8 tiles, 8x8 micro.
// mode 0: plain row-major C (ld = N)
// mode 1: headed store C[((b*Hn + h)*S + s)*D + d], h = n/64, d = n%64
// Requires M%128==0, N%128==0, K%8==0 (true for all calls here).
// ============================================================
#define BM  128
#define BN  128
#define BKK 8
#define TM  8
#define TN  8

__global__ __launch_bounds__(256) void sgemm_kernel(
    const float* __restrict__ A, const float* __restrict__ Bm, float* __restrict__ C,
    int Mdim, int Ndim, int Kdim, int mode, int Hn)
{
    __shared__ float As[BKK][BM];   // transposed: As[k][m]
    __shared__ float Bs[BKK][BN];

    const int tid = threadIdx.x;
    const int tx  = tid & 15;
    const int ty  = tid >> 4;
    const int bm  = blockIdx.y * BM;
    const int bn  = blockIdx.x * BN;

    const int aRow = tid >> 1;          // 0..127
    const int aCol = (tid & 1) * 4;     // 0 or 4
    const int bRow = tid >> 5;          // 0..7
    const int bCol = (tid & 31) * 4;    // 0..124

    const float* Ap = A  + (size_t)(bm + aRow) * Kdim + aCol;
    const float* Bp = Bm + (size_t)bRow * Ndim + bn + bCol;

    float acc[TM][TN];
    #pragma unroll
    for (int i = 0; i < TM; i++)
        #pragma unroll
        for (int j = 0; j < TN; j++) acc[i][j] = 0.f;

    for (int k0 = 0; k0 < Kdim; k0 += BKK) {
        float4 a4 = *(const float4*)(Ap + k0);
        float4 b4 = *(const float4*)(Bp + (size_t)k0 * Ndim);
        As[aCol + 0][aRow] = a4.x;
        As[aCol + 1][aRow] = a4.y;
        As[aCol + 2][aRow] = a4.z;
        As[aCol + 3][aRow] = a4.w;
        *(float4*)(&Bs[bRow][bCol]) = b4;
        __syncthreads();

        #pragma unroll
        for (int kk = 0; kk < BKK; kk++) {
            float a[TM], b[TN];
            *(float4*)&a[0] = *(const float4*)&As[kk][ty * TM];
            *(float4*)&a[4] = *(const float4*)&As[kk][ty * TM + 4];
            *(float4*)&b[0] = *(const float4*)&Bs[kk][tx * TN];
            *(float4*)&b[4] = *(const float4*)&Bs[kk][tx * TN + 4];
            #pragma unroll
            for (int i = 0; i < TM; i++)
                #pragma unroll
                for (int j = 0; j < TN; j++)
                    acc[i][j] = fmaf(a[i], b[j], acc[i][j]);
        }
        __syncthreads();
    }

    if (mode == 0) {
        #pragma unroll
        for (int i = 0; i < TM; i++) {
            float* Cp = C + (size_t)(bm + ty * TM + i) * Ndim + bn + tx * TN;
            *(float4*)(Cp)     = make_float4(acc[i][0], acc[i][1], acc[i][2], acc[i][3]);
            *(float4*)(Cp + 4) = make_float4(acc[i][4], acc[i][5], acc[i][6], acc[i][7]);
        }
    } else {
        #pragma unroll
        for (int i = 0; i < TM; i++) {
            int m  = bm + ty * TM + i;
            int bb = m / S_;
            int ss = m & (S_ - 1);
            #pragma unroll
            for (int j = 0; j < TN; j++) {
                int n  = bn + tx * TN + j;
                int hh = n >> 6;
                int dd = n & 63;
                C[(((size_t)bb * Hn + hh) * S_ + ss) * D_ + dd] = acc[i][j];
            }
        }
    }
}

// ============================================================
// Fused RMSNorm + RoPE, in place. buf layout: (rows, 64), row -> s = row % S.
// One warp per row; lane handles d=lane and d=lane+32.
// ============================================================
__global__ void rmsrope_kernel(float* __restrict__ buf,
                               const float* __restrict__ cosp,
                               const float* __restrict__ sinp,
                               const float* __restrict__ scale,
                               int totalRows, float outmult)
{
    int row  = blockIdx.x * (blockDim.x >> 5) + (threadIdx.x >> 5);
    int lane = threadIdx.x & 31;
    if (row >= totalRows) return;
    int s = row & (S_ - 1);
    float* p = buf + (size_t)row * D_;

    float v1 = p[lane];
    float v2 = p[lane + 32];
    float ss = v1 * v1 + v2 * v2;
    #pragma unroll
    for (int o = 16; o > 0; o >>= 1) ss += __shfl_xor_sync(0xffffffffu, ss, o);
    float inv = rsqrtf(ss * (1.0f / 64.0f) + 1e-6f);

    float n1 = v1 * inv * scale[lane];
    float n2 = v2 * inv * scale[lane + 32];
    float c1 = cosp[s * D_ + lane],      s1 = sinp[s * D_ + lane];
    float c2 = cosp[s * D_ + lane + 32], s2 = sinp[s * D_ + lane + 32];
    // rope: out[d] = x[d]*cos[d] - x[d+32]*sin[d]; out[d+32] = x[d+32]*cos[d+32] + x[d]*sin[d+32]
    p[lane]      = (n1 * c1 - n2 * s1) * outmult;
    p[lane + 32] = (n2 * c2 + n1 * s2) * outmult;
}

// ============================================================
// Causal flash attention, fp32. 64x64 tiles, 256 threads (16x16 grid of 4x4).
// Q pre-scaled by 1/sqrt(D). K/V layout (b,g,s,d). Output ctx (b,s,h,d).
// ============================================================
#define QS_STR 65
#define VS_STR 68

__global__ __launch_bounds__(256) void attn_kernel(
    const float* __restrict__ Q, const float* __restrict__ K,
    const float* __restrict__ V, float* __restrict__ CTX)
{
    extern __shared__ float sm[];
    float* Qs   = sm;                       // Qs[d*65 + r]
    float* Ks   = Qs + 64 * QS_STR;         // Ks[d*65 + c]
    float* Vs   = Ks + 64 * QS_STR;         // Vs[j*68 + d]
    float* Ps   = Vs + 64 * VS_STR;         // Ps[r*68 + j]
    float* arow = Ps + 64 * VS_STR;         // [64] alpha
    float* lrow = arow + 64;                // [64] 1/l

    const int tid = threadIdx.x;
    const int tx  = tid & 15;
    const int ty  = tid >> 4;
    const int qt  = blockIdx.x;
    const int bh  = blockIdx.y;
    const int b   = bh >> 5;   // / H_
    const int h   = bh & 31;
    const int g   = h >> 2;    // / GS_

    const float* Qbase = Q + (((size_t)b * H_ + h) * S_ + (size_t)qt * 64) * D_;
    const float* Kbase = K + (((size_t)b * G_ + g) * S_) * D_;
    const float* Vbase = V + (((size_t)b * G_ + g) * S_) * D_;

    for (int idx = tid; idx < 64 * 64; idx += 256) {
        int r = idx >> 6, d = idx & 63;
        Qs[d * QS_STR + r] = Qbase[r * D_ + d];
    }

    float m_r = -1e30f, l_r = 0.f;
    float o[4][4];
    #pragma unroll
    for (int i = 0; i < 4; i++)
        #pragma unroll
        for (int j = 0; j < 4; j++) o[i][j] = 0.f;

    __syncthreads();

    for (int kt = 0; kt <= qt; kt++) {
        for (int idx = tid; idx < 64 * 64; idx += 256) {
            int r = idx >> 6, d = idx & 63;
            size_t goff = ((size_t)kt * 64 + r) * D_ + d;
            Ks[d * QS_STR + r] = Kbase[goff];
            Vs[r * VS_STR + d] = Vbase[goff];
        }
        __syncthreads();

        float sacc[4][4];
        #pragma unroll
        for (int i = 0; i < 4; i++)
            #pragma unroll
            for (int j = 0; j < 4; j++) sacc[i][j] = 0.f;

        #pragma unroll 4
        for (int kk = 0; kk < 64; kk++) {
            float a[4], bb[4];
            #pragma unroll
            for (int i = 0; i < 4; i++) a[i]  = Qs[kk * QS_STR + ty * 4 + i];
            #pragma unroll
            for (int j = 0; j < 4; j++) bb[j] = Ks[kk * QS_STR + tx * 4 + j];
            #pragma unroll
            for (int i = 0; i < 4; i++)
                #pragma unroll
                for (int j = 0; j < 4; j++)
                    sacc[i][j] = fmaf(a[i], bb[j], sacc[i][j]);
        }

        if (kt == qt) {
            #pragma unroll
            for (int i = 0; i < 4; i++)
                #pragma unroll
                for (int j = 0; j < 4; j++)
                    if (tx * 4 + j > ty * 4 + i) sacc[i][j] = -1e30f;
        }

        #pragma unroll
        for (int i = 0; i < 4; i++)
            #pragma unroll
            for (int j = 0; j < 4; j++)
                Ps[(ty * 4 + i) * VS_STR + tx * 4 + j] = sacc[i][j];
        __syncthreads();

        if (tid < 64) {
            float* pr = Ps + tid * VS_STR;
            float mx = -1e30f;
            #pragma unroll 8
            for (int c = 0; c < 64; c++) mx = fmaxf(mx, pr[c]);
            float mnew  = fmaxf(m_r, mx);
            float alpha = __expf(m_r - mnew);
            float sum = 0.f;
            #pragma unroll 8
            for (int c = 0; c < 64; c++) {
                float e = __expf(pr[c] - mnew);
                pr[c] = e;
                sum += e;
            }
            l_r = l_r * alpha + sum;
            m_r = mnew;
            arow[tid] = alpha;
        }
        __syncthreads();

        float al[4];
        #pragma unroll
        for (int i = 0; i < 4; i++) al[i] = arow[ty * 4 + i];
        #pragma unroll
        for (int i = 0; i < 4; i++)
            #pragma unroll
            for (int j = 0; j < 4; j++) o[i][j] *= al[i];

        #pragma unroll 4
        for (int kk = 0; kk < 64; kk++) {
            float a[4];
            #pragma unroll
            for (int i = 0; i < 4; i++) a[i] = Ps[(ty * 4 + i) * VS_STR + kk];
            float4 v4 = *(const float4*)&Vs[kk * VS_STR + tx * 4];
            #pragma unroll
            for (int i = 0; i < 4; i++) {
                o[i][0] = fmaf(a[i], v4.x, o[i][0]);
                o[i][1] = fmaf(a[i], v4.y, o[i][1]);
                o[i][2] = fmaf(a[i], v4.z, o[i][2]);
                o[i][3] = fmaf(a[i], v4.w, o[i][3]);
            }
        }
        __syncthreads();
    }

    if (tid < 64) lrow[tid] = 1.0f / l_r;
    __syncthreads();

    #pragma unroll
    for (int i = 0; i < 4; i++) {
        int s = qt * 64 + ty * 4 + i;
        float invl = lrow[ty * 4 + i];
        float* Cp = CTX + (((size_t)b * S_ + s) * H_ + h) * D_ + tx * 4;
        *(float4*)Cp = make_float4(o[i][0] * invl, o[i][1] * invl,
                                   o[i][2] * invl, o[i][3] * invl);
    }
}

// ============================================================
// Launch
// ============================================================
extern "C" void kernel_launch(void* const* d_in, const int* in_sizes, int n_in,
                              void* d_out, int out_size)
{
    const float* x      = (const float*)d_in[0];
    // d_in[1] = mask (causal, implicit) — unused
    const float* cosp   = (const float*)d_in[2];
    const float* sinp   = (const float*)d_in[3];
    const float* Wq     = (const float*)d_in[4];
    const float* Wk     = (const float*)d_in[5];
    const float* Wv     = (const float*)d_in[6];
    const float* Wo     = (const float*)d_in[7];
    const float* qscale = (const float*)d_in[8];
    const float* kscale = (const float*)d_in[9];

    float* out  = (float*)d_out;             // (B,S,DIN)
    float* Kout = out + OUT_ELEMS;           // (B,G,S,D) normed+roped k
    float* Vout = Kout + KV_ELEMS;           // (B,G,S,D) raw v

    float *Qbuf, *Ctxbuf;
    cudaGetSymbolAddress((void**)&Qbuf, g_Q);
    cudaGetSymbolAddress((void**)&Ctxbuf, g_ctx);

    // QKV projections (headed layout stores)
    {
        dim3 gq(DIN_ / BN, M_ / BM);          // N=2048
        sgemm_kernel<<<gq, 256>>>(x, Wq, Qbuf, M_, H_ * D_, DIN_, 1, H_);
        dim3 gk((G_ * D_) / BN, M_ / BM);     // N=512
        sgemm_kernel<<<gk, 256>>>(x, Wk, Kout, M_, G_ * D_, DIN_, 1, G_);
        sgemm_kernel<<<gk, 256>>>(x, Wv, Vout, M_, G_ * D_, DIN_, 1, G_);
    }

    // RMSNorm + RoPE (q additionally scaled by 1/sqrt(D))
    {
        int qRows = B_ * H_ * S_;
        int kRows = B_ * G_ * S_;
        rmsrope_kernel<<<qRows / 8, 256>>>(Qbuf, cosp, sinp, qscale, qRows, 0.125f);
        rmsrope_kernel<<<kRows / 8, 256>>>(Kout, cosp, sinp, kscale, kRows, 1.0f);
    }

    // Attention
    {
        int smem = (64 * QS_STR * 2 + 64 * VS_STR * 2 + 128) * (int)sizeof(float);
        cudaFuncSetAttribute(attn_kernel, cudaFuncAttributeMaxDynamicSharedMemorySize, smem);
        dim3 ga(S_ / 64, B_ * H_);
        attn_kernel<<<ga, 256, smem>>>(Qbuf, Kout, Vout, Ctxbuf);
    }

    // Output projection
    {
        dim3 go(DIN_ / BN, M_ / BM);
        sgemm_kernel<<<go, 256>>>(Ctxbuf, Wo, out, M_, DIN_, H_ * D_, 0, 0);
    }
}

// round 3
// speedup vs baseline: 4.1308x; 4.1308x over previous
#include <cuda_runtime.h>
#include <cuda_fp16.h>
#include <cstdint>
#include <math.h>

#define B_   2
#define S_   2048
#define DIN_ 2048
#define H_   32
#define G_   8
#define D_   64
#define M_   (B_*S_)

#define OUT_ELEMS ((size_t)B_*S_*DIN_)
#define KV_ELEMS  ((size_t)B_*G_*S_*D_)

// ---------------- scratch (static device arrays) ----------------
__device__ __half g_xh [(size_t)M_*DIN_];
__device__ __half g_Wqt[(size_t)DIN_*H_*D_];   // [n][k]
__device__ __half g_Wkt[(size_t)G_*D_*DIN_];
__device__ __half g_Wvt[(size_t)G_*D_*DIN_];
__device__ __half g_Wot[(size_t)DIN_*H_*D_];   // [n=DIN][k=H*D]
__device__ float  g_Qf [(size_t)B_*H_*S_*D_];  // fp32 (b,h,s,d)
__device__ __half g_Qh [(size_t)B_*H_*S_*D_];  // half, pre-scaled 1/8
__device__ __half g_Kh [KV_ELEMS];             // (b,g,s,d)
__device__ __half g_Vt [KV_ELEMS];             // (b,g,d,s)  transposed
__device__ __half g_ctxh[(size_t)M_*H_*D_];    // (b,s,h,d)

// ---------------- PTX helpers ----------------
__device__ __forceinline__ void cp16(void* s, const void* g){
    uint32_t sa = (uint32_t)__cvta_generic_to_shared(s);
    asm volatile("cp.async.cg.shared.global [%0], [%1], 16;\n" :: "r"(sa), "l"(g));
}
__device__ __forceinline__ void cp_commit(){ asm volatile("cp.async.commit_group;\n"); }
template<int N> __device__ __forceinline__ void cp_wait(){
    asm volatile("cp.async.wait_group %0;\n" :: "n"(N));
}
__device__ __forceinline__ void mma16816(float* c, const uint32_t* a, const uint32_t* b){
    asm volatile("mma.sync.aligned.m16n8k16.row.col.f32.f16.f16.f32 "
        "{%0,%1,%2,%3},{%4,%5,%6,%7},{%8,%9},{%0,%1,%2,%3};\n"
        : "+f"(c[0]),"+f"(c[1]),"+f"(c[2]),"+f"(c[3])
        : "r"(a[0]),"r"(a[1]),"r"(a[2]),"r"(a[3]),"r"(b[0]),"r"(b[1]));
}

// ---------------- conversion kernels ----------------
__global__ void f2h_kernel(const float* __restrict__ in, __half* __restrict__ out, int n4){
    int i = blockIdx.x * blockDim.x + threadIdx.x;
    if (i >= n4) return;
    float4 v = *(const float4*)(in + (size_t)i*4);
    __half* o = out + (size_t)i*4;
    o[0]=__float2half_rn(v.x); o[1]=__float2half_rn(v.y);
    o[2]=__float2half_rn(v.z); o[3]=__float2half_rn(v.w);
}

// W[k][n] (K x N fp32) -> Wt[n][k] half
__global__ void wtrans_kernel(const float* __restrict__ W, __half* __restrict__ Wt, int K, int N){
    __shared__ float t[32][33];
    int n0 = blockIdx.x*32, k0 = blockIdx.y*32;
    for (int j = threadIdx.y; j < 32; j += 8)
        t[j][threadIdx.x] = W[(size_t)(k0+j)*N + n0 + threadIdx.x];
    __syncthreads();
    for (int j = threadIdx.y; j < 32; j += 8)
        Wt[(size_t)(n0+j)*K + k0 + threadIdx.x] = __float2half_rn(t[threadIdx.x][j]);
}

// V (bg, s, d) fp32 -> Vt (bg, d, s) half
__global__ void vtrans_kernel(const float* __restrict__ V, __half* __restrict__ Vt){
    __shared__ float t[32][33];
    int s0 = blockIdx.x*32, d0 = blockIdx.y*32, bg = blockIdx.z;
    const float* Vb = V + (size_t)bg*S_*D_;
    __half* Vo = Vt + (size_t)bg*S_*D_;
    for (int j = threadIdx.y; j < 32; j += 8)
        t[j][threadIdx.x] = Vb[(size_t)(s0+j)*D_ + d0 + threadIdx.x];
    __syncthreads();
    for (int j = threadIdx.y; j < 32; j += 8)
        Vo[(size_t)(d0+j)*S_ + s0 + threadIdx.x] = __float2half_rn(t[threadIdx.x][j]);
}

// ---------------- HGEMM: C(fp32) = A(half, MxK) @ Bt(half, NxK)^T ----------------
#define GBM 128
#define GBN 128
#define GBK 32
#define AST 40
#define BST 40

__global__ __launch_bounds__(256,2) void hgemm_kernel(
    const __half* __restrict__ A, const __half* __restrict__ Bt, float* __restrict__ C,
    int Ndim, int Kdim, int mode, int Hn)
{
    __shared__ __half As[2][GBM][AST];
    __shared__ __half Bs[2][GBN][BST];
    const int tid = threadIdx.x, lane = tid & 31, wid = tid >> 5;
    const int wm = (wid & 1) * 64, wn = (wid >> 1) * 32;
    const int bm = blockIdx.y * GBM, bn = blockIdx.x * GBN;

    const int ldRow = tid >> 1;
    const int ldOff = (tid & 1) * 16;
    const __half* Ap = A  + (size_t)(bm + ldRow) * Kdim + ldOff;
    const __half* Bp = Bt + (size_t)(bn + ldRow) * Kdim + ldOff;

    float acc[4][4][4];
    #pragma unroll
    for (int mi=0; mi<4; mi++)
        #pragma unroll
        for (int ni=0; ni<4; ni++)
            #pragma unroll
            for (int r=0; r<4; r++) acc[mi][ni][r] = 0.f;

    {   // prologue
        cp16(&As[0][ldRow][ldOff],   Ap);
        cp16(&As[0][ldRow][ldOff+8], Ap + 8);
        cp16(&Bs[0][ldRow][ldOff],   Bp);
        cp16(&Bs[0][ldRow][ldOff+8], Bp + 8);
        cp_commit();
    }

    const int nk = Kdim / GBK;
    for (int it = 0; it < nk; ++it){
        const int st = it & 1;
        if (it + 1 < nk){
            int k0 = (it + 1) * GBK;
            cp16(&As[st^1][ldRow][ldOff],   Ap + k0);
            cp16(&As[st^1][ldRow][ldOff+8], Ap + k0 + 8);
            cp16(&Bs[st^1][ldRow][ldOff],   Bp + k0);
            cp16(&Bs[st^1][ldRow][ldOff+8], Bp + k0 + 8);
            cp_commit();
            cp_wait<1>();
        } else {
            cp_wait<0>();
        }
        __syncthreads();

        #pragma unroll
        for (int ks = 0; ks < 2; ks++){
            const int kk = ks * 16;
            uint32_t a[4][4], b[4][2];
            #pragma unroll
            for (int mi = 0; mi < 4; mi++){
                int r = wm + mi*16 + (lane >> 2);
                int c = kk + (lane & 3) * 2;
                a[mi][0] = *(const uint32_t*)&As[st][r  ][c  ];
                a[mi][1] = *(const uint32_t*)&As[st][r+8][c  ];
                a[mi][2] = *(const uint32_t*)&As[st][r  ][c+8];
                a[mi][3] = *(const uint32_t*)&As[st][r+8][c+8];
            }
            #pragma unroll
            for (int ni = 0; ni < 4; ni++){
                int n = wn + ni*8 + (lane >> 2);
                int c = kk + (lane & 3) * 2;
                b[ni][0] = *(const uint32_t*)&Bs[st][n][c  ];
                b[ni][1] = *(const uint32_t*)&Bs[st][n][c+8];
            }
            #pragma unroll
            for (int mi = 0; mi < 4; mi++)
                #pragma unroll
                for (int ni = 0; ni < 4; ni++)
                    mma16816(acc[mi][ni], a[mi], b[ni]);
        }
        __syncthreads();
    }

    // epilogue
    if (mode == 0){
        #pragma unroll
        for (int mi = 0; mi < 4; mi++)
            #pragma unroll
            for (int ni = 0; ni < 4; ni++){
                int r = bm + wm + mi*16 + (lane >> 2);
                int c = bn + wn + ni*8 + (lane & 3)*2;
                *(float2*)&C[(size_t)r*Ndim + c]     = make_float2(acc[mi][ni][0], acc[mi][ni][1]);
                *(float2*)&C[(size_t)(r+8)*Ndim + c] = make_float2(acc[mi][ni][2], acc[mi][ni][3]);
            }
    } else {
        #pragma unroll
        for (int mi = 0; mi < 4; mi++)
            #pragma unroll
            for (int ni = 0; ni < 4; ni++){
                int r = bm + wm + mi*16 + (lane >> 2);
                int c = bn + wn + ni*8 + (lane & 3)*2;
                int bb = r >> 11;
                int hh = c >> 6, dd = c & 63;
                size_t base = (((size_t)bb*Hn + hh)*S_ + (r & (S_-1)))*D_ + dd;
                *(float2*)&C[base] = make_float2(acc[mi][ni][0], acc[mi][ni][1]);
                size_t base2 = (((size_t)bb*Hn + hh)*S_ + ((r+8) & (S_-1)))*D_ + dd;
                *(float2*)&C[base2] = make_float2(acc[mi][ni][2], acc[mi][ni][3]);
            }
    }
}

// ---------------- fused RMSNorm + RoPE (+half convert) ----------------
__global__ void rmsrope2_kernel(const float* __restrict__ in, float* __restrict__ outf,
                                __half* __restrict__ outh,
                                const float* __restrict__ cosp, const float* __restrict__ sinp,
                                const float* __restrict__ scale, int totalRows, float mult)
{
    int row  = blockIdx.x * (blockDim.x >> 5) + (threadIdx.x >> 5);
    int lane = threadIdx.x & 31;
    if (row >= totalRows) return;
    int s = row & (S_ - 1);
    const float* p = in + (size_t)row * D_;
    float v1 = p[lane], v2 = p[lane + 32];
    float ss = v1*v1 + v2*v2;
    #pragma unroll
    for (int o = 16; o > 0; o >>= 1) ss += __shfl_xor_sync(0xffffffffu, ss, o);
    float inv = rsqrtf(ss * (1.0f/64.0f) + 1e-6f);
    float n1 = v1 * inv * scale[lane];
    float n2 = v2 * inv * scale[lane + 32];
    float c1 = cosp[s*D_ + lane],      s1 = sinp[s*D_ + lane];
    float c2 = cosp[s*D_ + lane + 32], s2 = sinp[s*D_ + lane + 32];
    float o1 = n1*c1 - n2*s1;
    float o2 = n2*c2 + n1*s2;
    if (outf){
        outf[(size_t)row*D_ + lane]      = o1;
        outf[(size_t)row*D_ + lane + 32] = o2;
    }
    outh[(size_t)row*D_ + lane]      = __float2half_rn(o1 * mult);
    outh[(size_t)row*D_ + lane + 32] = __float2half_rn(o2 * mult);
}

// ---------------- Flash attention with fp16 mma ----------------
#define AQST 72   // halves
#define AKST 72
#define AVST 72
#define ASST 68   // floats
#define APST 72   // halves

__global__ __launch_bounds__(256) void attn_mma_kernel(
    const __half* __restrict__ Qh, const __half* __restrict__ Kh,
    const __half* __restrict__ Vt, __half* __restrict__ CTX)
{
    extern __shared__ char smraw[];
    __half* Qs = (__half*)smraw;                 // [64][AQST]
    __half* Ks = Qs + 64*AQST;                   // [2][64][AKST]
    __half* Vs = Ks + 2*64*AKST;                 // [2][64][AVST]
    float*  Ss = (float*)(Vs + 2*64*AVST);       // [64][ASST]   S^T: [key][q]
    __half* Ph = (__half*)(Ss + 64*ASST);        // [64][APST]   P: [q][key]
    float* arow = (float*)(Ph + 64*APST);        // [64]
    float* lrow = arow + 64;                     // [64]

    const int tid = threadIdx.x, lane = tid & 31, wid = tid >> 5;
    const int wm = (wid & 1) * 32;     // S^T row (key) tile / O row (q) tile
    const int wn = (wid >> 1) * 16;    // S^T col (q) tile  / O col (d) tile
    const int qt = blockIdx.x, bh = blockIdx.y;
    const int b = bh >> 5, h = bh & 31, g = h >> 2;

    const __half* Qbase = Qh + (((size_t)b*H_ + h)*S_ + (size_t)qt*64) * D_;
    const __half* Kbase = Kh + ((size_t)b*G_ + g) * (size_t)S_ * D_;
    const __half* Vbase = Vt + ((size_t)b*G_ + g) * (size_t)D_ * S_;

    const int lr = tid >> 2;            // 0..63
    const int lo = (tid & 3) * 16;      // halves

    // prologue: Q + K/V(kt=0)
    cp16(&Qs[lr*AQST + lo],     Qbase + (size_t)lr*D_ + lo);
    cp16(&Qs[lr*AQST + lo + 8], Qbase + (size_t)lr*D_ + lo + 8);
    {
        const __half* kp = Kbase + (size_t)lr*D_ + lo;
        cp16(&Ks[lr*AKST + lo],     kp);
        cp16(&Ks[lr*AKST + lo + 8], kp + 8);
        const __half* vp = Vbase + (size_t)lr*S_ + lo;
        cp16(&Vs[lr*AVST + lo],     vp);
        cp16(&Vs[lr*AVST + lo + 8], vp + 8);
    }
    cp_commit();

    float m_r = -1e30f, l_r = 0.f;
    float o[2][2][4];
    #pragma unroll
    for (int mi=0;mi<2;mi++)
        #pragma unroll
        for (int ni=0;ni<2;ni++)
            #pragma unroll
            for (int r=0;r<4;r++) o[mi][ni][r] = 0.f;

    for (int kt = 0; kt <= qt; ++kt){
        const int st = kt & 1;
        if (kt < qt){
            const int sn = st ^ 1;
            const __half* kp = Kbase + ((size_t)(kt+1)*64 + lr)*D_ + lo;
            cp16(&Ks[(sn*64 + lr)*AKST + lo],     kp);
            cp16(&Ks[(sn*64 + lr)*AKST + lo + 8], kp + 8);
            const __half* vp = Vbase + (size_t)lr*S_ + (size_t)(kt+1)*64 + lo;
            cp16(&Vs[(sn*64 + lr)*AVST + lo],     vp);
            cp16(&Vs[(sn*64 + lr)*AVST + lo + 8], vp + 8);
            cp_commit();
            cp_wait<1>();
        } else {
            cp_wait<0>();
        }
        __syncthreads();

        // ---- S^T = K_tile @ Q^T  (A = K [key][d], B = Q [q][d]) ----
        float sc[2][2][4];
        #pragma unroll
        for (int mi=0;mi<2;mi++)
            #pragma unroll
            for (int ni=0;ni<2;ni++)
                #pragma unroll
                for (int r=0;r<4;r++) sc[mi][ni][r] = 0.f;

        #pragma unroll
        for (int ks = 0; ks < 4; ks++){
            const int kk = ks * 16;
            uint32_t a[2][4], bf[2][2];
            #pragma unroll
            for (int mi = 0; mi < 2; mi++){
                int r = wm + mi*16 + (lane >> 2);
                int c = kk + (lane & 3)*2;
                a[mi][0] = *(const uint32_t*)&Ks[(st*64 + r  )*AKST + c  ];
                a[mi][1] = *(const uint32_t*)&Ks[(st*64 + r+8)*AKST + c  ];
                a[mi][2] = *(const uint32_t*)&Ks[(st*64 + r  )*AKST + c+8];
                a[mi][3] = *(const uint32_t*)&Ks[(st*64 + r+8)*AKST + c+8];
            }
            #pragma unroll
            for (int ni = 0; ni < 2; ni++){
                int n = wn + ni*8 + (lane >> 2);
                int c = kk + (lane & 3)*2;
                bf[ni][0] = *(const uint32_t*)&Qs[n*AQST + c  ];
                bf[ni][1] = *(const uint32_t*)&Qs[n*AQST + c+8];
            }
            #pragma unroll
            for (int mi = 0; mi < 2; mi++)
                #pragma unroll
                for (int ni = 0; ni < 2; ni++)
                    mma16816(sc[mi][ni], a[mi], bf[ni]);
        }

        // mask (key > q) on last tile, store to Ss[key][q]
        #pragma unroll
        for (int mi = 0; mi < 2; mi++)
            #pragma unroll
            for (int ni = 0; ni < 2; ni++){
                int key = wm + mi*16 + (lane >> 2);
                int q   = wn + ni*8  + (lane & 3)*2;
                float v0 = sc[mi][ni][0], v1 = sc[mi][ni][1];
                float v2 = sc[mi][ni][2], v3 = sc[mi][ni][3];
                if (kt == qt){
                    if (q     < key)     v0 = -1e30f;
                    if (q + 1 < key)     v1 = -1e30f;
                    if (q     < key + 8) v2 = -1e30f;
                    if (q + 1 < key + 8) v3 = -1e30f;
                }
                *(float2*)&Ss[key*ASST + q]     = make_float2(v0, v1);
                *(float2*)&Ss[(key+8)*ASST + q] = make_float2(v2, v3);
            }
        __syncthreads();

        // ---- online softmax: thread q owns column q of S^T ----
        if (tid < 64){
            const int q = tid;
            float mx = -1e30f;
            #pragma unroll 8
            for (int c = 0; c < 64; c++) mx = fmaxf(mx, Ss[c*ASST + q]);
            float mnew  = fmaxf(m_r, mx);
            float alpha = __expf(m_r - mnew);
            float sum = 0.f;
            #pragma unroll 4
            for (int j = 0; j < 32; j++){
                int c2 = (j + q) & 31;          // rotated -> conflict-free Ph writes
                float e0 = __expf(Ss[(2*c2  )*ASST + q] - mnew);
                float e1 = __expf(Ss[(2*c2+1)*ASST + q] - mnew);
                __half h0 = __float2half_rn(e0), h1 = __float2half_rn(e1);
                sum += __half2float(h0) + __half2float(h1);
                *(__half2*)&Ph[q*APST + 2*c2] = __halves2half2(h0, h1);
            }
            l_r = l_r * alpha + sum;
            m_r = mnew;
            arow[q] = alpha;
        }
        __syncthreads();

        // ---- rescale O, then O += P @ V  (A = P [q][key], B = Vt [d][key]) ----
        #pragma unroll
        for (int mi = 0; mi < 2; mi++){
            int r = wm + mi*16 + (lane >> 2);
            float a0 = arow[r], a1 = arow[r + 8];
            #pragma unroll
            for (int ni = 0; ni < 2; ni++){
                o[mi][ni][0] *= a0; o[mi][ni][1] *= a0;
                o[mi][ni][2] *= a1; o[mi][ni][3] *= a1;
            }
        }
        #pragma unroll
        for (int ks = 0; ks < 4; ks++){
            const int kk = ks * 16;
            uint32_t a[2][4], bf[2][2];
            #pragma unroll
            for (int mi = 0; mi < 2; mi++){
                int r = wm + mi*16 + (lane >> 2);
                int c = kk + (lane & 3)*2;
                a[mi][0] = *(const uint32_t*)&Ph[(r  )*APST + c  ];
                a[mi][1] = *(const uint32_t*)&Ph[(r+8)*APST + c  ];
                a[mi][2] = *(const uint32_t*)&Ph[(r  )*APST + c+8];
                a[mi][3] = *(const uint32_t*)&Ph[(r+8)*APST + c+8];
            }
            #pragma unroll
            for (int ni = 0; ni < 2; ni++){
                int n = wn + ni*8 + (lane >> 2);   // d index
                int c = kk + (lane & 3)*2;         // key pair
                bf[ni][0] = *(const uint32_t*)&Vs[(st*64 + n)*AVST + c  ];
                bf[ni][1] = *(const uint32_t*)&Vs[(st*64 + n)*AVST + c+8];
            }
            #pragma unroll
            for (int mi = 0; mi < 2; mi++)
                #pragma unroll
                for (int ni = 0; ni < 2; ni++)
                    mma16816(o[mi][ni], a[mi], bf[ni]);
        }
        __syncthreads();
    }

    if (tid < 64) lrow[tid] = 1.0f / l_r;
    __syncthreads();

    // store ctx (b,s,h,d) as half
    #pragma unroll
    for (int mi = 0; mi < 2; mi++)
        #pragma unroll
        for (int ni = 0; ni < 2; ni++){
            int q = wm + mi*16 + (lane >> 2);
            int d = wn + ni*8  + (lane & 3)*2;
            int s0 = qt*64 + q;
            float i0 = lrow[q], i1 = lrow[q + 8];
            __half2 h01 = __halves2half2(__float2half_rn(o[mi][ni][0] * i0),
                                         __float2half_rn(o[mi][ni][1] * i0));
            __half2 h23 = __halves2half2(__float2half_rn(o[mi][ni][2] * i1),
                                         __float2half_rn(o[mi][ni][3] * i1));
            *(__half2*)&CTX[(((size_t)b*S_ + s0    )*H_ + h)*D_ + d] = h01;
            *(__half2*)&CTX[(((size_t)b*S_ + s0 + 8)*H_ + h)*D_ + d] = h23;
        }
}

// ---------------- launch ----------------
extern "C" void kernel_launch(void* const* d_in, const int* in_sizes, int n_in,
                              void* d_out, int out_size)
{
    const float* x      = (const float*)d_in[0];
    const float* cosp   = (const float*)d_in[2];
    const float* sinp   = (const float*)d_in[3];
    const float* Wq     = (const float*)d_in[4];
    const float* Wk     = (const float*)d_in[5];
    const float* Wv     = (const float*)d_in[6];
    const float* Wo     = (const float*)d_in[7];
    const float* qscale = (const float*)d_in[8];
    const float* kscale = (const float*)d_in[9];

    float* out  = (float*)d_out;
    float* Kout = out + OUT_ELEMS;
    float* Vout = Kout + KV_ELEMS;

    __half *xh, *Wqt, *Wkt, *Wvt, *Wot, *Qh, *Kh, *Vt, *ctxh;
    float *Qf;
    cudaGetSymbolAddress((void**)&xh,  g_xh);
    cudaGetSymbolAddress((void**)&Wqt, g_Wqt);
    cudaGetSymbolAddress((void**)&Wkt, g_Wkt);
    cudaGetSymbolAddress((void**)&Wvt, g_Wvt);
    cudaGetSymbolAddress((void**)&Wot, g_Wot);
    cudaGetSymbolAddress((void**)&Qf,  g_Qf);
    cudaGetSymbolAddress((void**)&Qh,  g_Qh);
    cudaGetSymbolAddress((void**)&Kh,  g_Kh);
    cudaGetSymbolAddress((void**)&Vt,  g_Vt);
    cudaGetSymbolAddress((void**)&ctxh, g_ctxh);

    // convert inputs
    {
        int n4 = (M_*DIN_)/4;
        f2h_kernel<<<(n4+255)/256, 256>>>(x, xh, n4);
        dim3 tb(32,8);
        wtrans_kernel<<<dim3((H_*D_)/32, DIN_/32), tb>>>(Wq, Wqt, DIN_, H_*D_);
        wtrans_kernel<<<dim3((G_*D_)/32, DIN_/32), tb>>>(Wk, Wkt, DIN_, G_*D_);
        wtrans_kernel<<<dim3((G_*D_)/32, DIN_/32), tb>>>(Wv, Wvt, DIN_, G_*D_);
        wtrans_kernel<<<dim3(DIN_/32, (H_*D_)/32), tb>>>(Wo, Wot, H_*D_, DIN_);
    }

    // projections
    hgemm_kernel<<<dim3((H_*D_)/GBN, M_/GBM), 256>>>(xh, Wqt, Qf,   H_*D_, DIN_, 1, H_);
    hgemm_kernel<<<dim3((G_*D_)/GBN, M_/GBM), 256>>>(xh, Wkt, Kout, G_*D_, DIN_, 1, G_);
    hgemm_kernel<<<dim3((G_*D_)/GBN, M_/GBM), 256>>>(xh, Wvt, Vout, G_*D_, DIN_, 1, G_);

    // rmsnorm + rope (+half), V transpose
    rmsrope2_kernel<<<(B_*H_*S_)/8, 256>>>(Qf, nullptr, Qh, cosp, sinp, qscale, B_*H_*S_, 0.125f);
    rmsrope2_kernel<<<(B_*G_*S_)/8, 256>>>(Kout, Kout, Kh, cosp, sinp, kscale, B_*G_*S_, 1.0f);
    vtrans_kernel<<<dim3(S_/32, D_/32, B_*G_), dim3(32,8)>>>(Vout, Vt);

    // attention
    {
        int smem = 64*AQST*2 + 2*64*AKST*2 + 2*64*AVST*2 + 64*ASST*4 + 64*APST*2 + 2*64*4;
        cudaFuncSetAttribute(attn_mma_kernel, cudaFuncAttributeMaxDynamicSharedMemorySize, smem);
        attn_mma_kernel<<<dim3(S_/64, B_*H_), 256, smem>>>(Qh, Kh, Vt, ctxh);
    }

    // output projection
    hgemm_kernel<<<dim3(DIN_/GBN, M_/GBM), 256>>>(ctxh, Wot, out, DIN_, H_*D_, 0, 0);
}

// round 4
// speedup vs baseline: 4.5075x; 1.0912x over previous
#include <cuda_runtime.h>
#include <cuda_fp16.h>
#include <cstdint>
#include <math.h>

#define B_   2
#define S_   2048
#define DIN_ 2048
#define H_   32
#define G_   8
#define D_   64
#define M_   (B_*S_)

#define OUT_ELEMS ((size_t)B_*S_*DIN_)
#define KV_ELEMS  ((size_t)B_*G_*S_*D_)

// ---------------- scratch ----------------
__device__ __half g_xh [(size_t)M_*DIN_];
__device__ __half g_Wqt[(size_t)DIN_*H_*D_];
__device__ __half g_Wkt[(size_t)G_*D_*DIN_];
__device__ __half g_Wvt[(size_t)G_*D_*DIN_];
__device__ __half g_Wot[(size_t)DIN_*H_*D_];
__device__ float  g_Qf [(size_t)B_*H_*S_*D_];
__device__ __half g_Qh [(size_t)B_*H_*S_*D_];
__device__ __half g_Kh [KV_ELEMS];
__device__ __half g_Vt [KV_ELEMS];
__device__ __half g_ctxh[(size_t)M_*H_*D_];

// ---------------- PTX helpers ----------------
__device__ __forceinline__ void cp16(void* s, const void* g){
    uint32_t sa = (uint32_t)__cvta_generic_to_shared(s);
    asm volatile("cp.async.cg.shared.global [%0], [%1], 16;\n" :: "r"(sa), "l"(g));
}
__device__ __forceinline__ void cp_commit(){ asm volatile("cp.async.commit_group;\n"); }
template<int N> __device__ __forceinline__ void cp_wait(){
    asm volatile("cp.async.wait_group %0;\n" :: "n"(N));
}
__device__ __forceinline__ void mma16816(float* c, const uint32_t* a, const uint32_t* b){
    asm volatile("mma.sync.aligned.m16n8k16.row.col.f32.f16.f16.f32 "
        "{%0,%1,%2,%3},{%4,%5,%6,%7},{%8,%9},{%0,%1,%2,%3};\n"
        : "+f"(c[0]),"+f"(c[1]),"+f"(c[2]),"+f"(c[3])
        : "r"(a[0]),"r"(a[1]),"r"(a[2]),"r"(a[3]),"r"(b[0]),"r"(b[1]));
}
__device__ __forceinline__ void ldsm4(uint32_t* r, const __half* p){
    uint32_t a = (uint32_t)__cvta_generic_to_shared(p);
    asm volatile("ldmatrix.sync.aligned.m8n8.x4.shared.b16 {%0,%1,%2,%3}, [%4];"
        : "=r"(r[0]),"=r"(r[1]),"=r"(r[2]),"=r"(r[3]) : "r"(a));
}

// ---------------- conversion kernels ----------------
__global__ void f2h_kernel(const float* __restrict__ in, __half* __restrict__ out, int n4){
    int i = blockIdx.x * blockDim.x + threadIdx.x;
    if (i >= n4) return;
    float4 v = *(const float4*)(in + (size_t)i*4);
    __half* o = out + (size_t)i*4;
    o[0]=__float2half_rn(v.x); o[1]=__float2half_rn(v.y);
    o[2]=__float2half_rn(v.z); o[3]=__float2half_rn(v.w);
}

__global__ void wtrans_kernel(const float* __restrict__ W, __half* __restrict__ Wt, int K, int N){
    __shared__ float t[32][33];
    int n0 = blockIdx.x*32, k0 = blockIdx.y*32;
    for (int j = threadIdx.y; j < 32; j += 8)
        t[j][threadIdx.x] = W[(size_t)(k0+j)*N + n0 + threadIdx.x];
    __syncthreads();
    for (int j = threadIdx.y; j < 32; j += 8)
        Wt[(size_t)(n0+j)*K + k0 + threadIdx.x] = __float2half_rn(t[threadIdx.x][j]);
}

__global__ void vtrans_kernel(const float* __restrict__ V, __half* __restrict__ Vt){
    __shared__ float t[32][33];
    int s0 = blockIdx.x*32, d0 = blockIdx.y*32, bg = blockIdx.z;
    const float* Vb = V + (size_t)bg*S_*D_;
    __half* Vo = Vt + (size_t)bg*S_*D_;
    for (int j = threadIdx.y; j < 32; j += 8)
        t[j][threadIdx.x] = Vb[(size_t)(s0+j)*D_ + d0 + threadIdx.x];
    __syncthreads();
    for (int j = threadIdx.y; j < 32; j += 8)
        Vo[(size_t)(d0+j)*S_ + s0 + threadIdx.x] = __float2half_rn(t[threadIdx.x][j]);
}

// ---------------- HGEMM: 3-stage cp.async + ldmatrix ----------------
#define GBM 128
#define GBN 128
#define GBK 32
#define GST 40      // smem row stride (halves); 80B rows -> conflict-free LDSM

__global__ __launch_bounds__(256,2) void hgemm_kernel(
    const __half* __restrict__ A, const __half* __restrict__ Bt, float* __restrict__ C,
    int Ndim, int Kdim, int mode, int Hn)
{
    extern __shared__ __half hs[];
    __half* As = hs;                       // [3][128][GST]
    __half* Bs = hs + 3*GBM*GST;           // [3][128][GST]

    const int tid = threadIdx.x, lane = tid & 31, wid = tid >> 5;
    const int wm = (wid & 1) * 64, wn = (wid >> 1) * 32;
    const int bm = blockIdx.y * GBM, bn = blockIdx.x * GBN;

    const int ldRow = tid >> 1;
    const int ldOff = (tid & 1) * 16;
    const __half* Ap = A  + (size_t)(bm + ldRow) * Kdim + ldOff;
    const __half* Bp = Bt + (size_t)(bn + ldRow) * Kdim + ldOff;

    const int l16 = lane & 15, lh = lane >> 4;     // a-frag address parts
    const int g8h = lane >> 3, l8 = lane & 7;      // b-frag address parts

    float acc[4][4][4];
    #pragma unroll
    for (int mi=0; mi<4; mi++)
        #pragma unroll
        for (int ni=0; ni<4; ni++)
            #pragma unroll
            for (int r=0; r<4; r++) acc[mi][ni][r] = 0.f;

    const int nk = Kdim / GBK;
    // prologue: stages 0,1
    #pragma unroll
    for (int s = 0; s < 2; s++){
        int k0 = s * GBK;
        cp16(&As[(s*GBM + ldRow)*GST + ldOff],     Ap + k0);
        cp16(&As[(s*GBM + ldRow)*GST + ldOff + 8], Ap + k0 + 8);
        cp16(&Bs[(s*GBN + ldRow)*GST + ldOff],     Bp + k0);
        cp16(&Bs[(s*GBN + ldRow)*GST + ldOff + 8], Bp + k0 + 8);
        cp_commit();
    }

    for (int it = 0; it < nk; ++it){
        const int st = it % 3;
        if (it + 2 < nk){
            int sn = (it + 2) % 3;
            int k0 = (it + 2) * GBK;
            cp16(&As[(sn*GBM + ldRow)*GST + ldOff],     Ap + k0);
            cp16(&As[(sn*GBM + ldRow)*GST + ldOff + 8], Ap + k0 + 8);
            cp16(&Bs[(sn*GBN + ldRow)*GST + ldOff],     Bp + k0);
            cp16(&Bs[(sn*GBN + ldRow)*GST + ldOff + 8], Bp + k0 + 8);
            cp_commit();
            cp_wait<2>();
        } else {
            cp_wait<0>();
        }
        __syncthreads();

        #pragma unroll
        for (int ks = 0; ks < 2; ks++){
            const int kk = ks * 16;
            uint32_t a[4][4], bq[2][4];
            #pragma unroll
            for (int mi = 0; mi < 4; mi++)
                ldsm4(a[mi], &As[(st*GBM + wm + mi*16 + l16)*GST + kk + lh*8]);
            #pragma unroll
            for (int ni2 = 0; ni2 < 2; ni2++)
                ldsm4(bq[ni2], &Bs[(st*GBN + wn + ni2*16 + (g8h>>1)*8 + l8)*GST + kk + (g8h&1)*8]);
            #pragma unroll
            for (int mi = 0; mi < 4; mi++)
                #pragma unroll
                for (int ni = 0; ni < 4; ni++)
                    mma16816(acc[mi][ni], a[mi], &bq[ni>>1][(ni&1)*2]);
        }
        __syncthreads();
    }

    if (mode == 0){
        #pragma unroll
        for (int mi = 0; mi < 4; mi++)
            #pragma unroll
            for (int ni = 0; ni < 4; ni++){
                int r = bm + wm + mi*16 + (lane >> 2);
                int c = bn + wn + ni*8 + (lane & 3)*2;
                *(float2*)&C[(size_t)r*Ndim + c]     = make_float2(acc[mi][ni][0], acc[mi][ni][1]);
                *(float2*)&C[(size_t)(r+8)*Ndim + c] = make_float2(acc[mi][ni][2], acc[mi][ni][3]);
            }
    } else {
        #pragma unroll
        for (int mi = 0; mi < 4; mi++)
            #pragma unroll
            for (int ni = 0; ni < 4; ni++){
                int r = bm + wm + mi*16 + (lane >> 2);
                int c = bn + wn + ni*8 + (lane & 3)*2;
                int bb = r >> 11;
                int hh = c >> 6, dd = c & 63;
                size_t base = (((size_t)bb*Hn + hh)*S_ + (r & (S_-1)))*D_ + dd;
                *(float2*)&C[base] = make_float2(acc[mi][ni][0], acc[mi][ni][1]);
                size_t base2 = (((size_t)bb*Hn + hh)*S_ + ((r+8) & (S_-1)))*D_ + dd;
                *(float2*)&C[base2] = make_float2(acc[mi][ni][2], acc[mi][ni][3]);
            }
    }
}

// ---------------- fused RMSNorm + RoPE ----------------
__global__ void rmsrope2_kernel(const float* __restrict__ in, float* __restrict__ outf,
                                __half* __restrict__ outh,
                                const float* __restrict__ cosp, const float* __restrict__ sinp,
                                const float* __restrict__ scale, int totalRows, float mult)
{
    int row  = blockIdx.x * (blockDim.x >> 5) + (threadIdx.x >> 5);
    int lane = threadIdx.x & 31;
    if (row >= totalRows) return;
    int s = row & (S_ - 1);
    const float* p = in + (size_t)row * D_;
    float v1 = p[lane], v2 = p[lane + 32];
    float ss = v1*v1 + v2*v2;
    #pragma unroll
    for (int o = 16; o > 0; o >>= 1) ss += __shfl_xor_sync(0xffffffffu, ss, o);
    float inv = rsqrtf(ss * (1.0f/64.0f) + 1e-6f);
    float n1 = v1 * inv * scale[lane];
    float n2 = v2 * inv * scale[lane + 32];
    float c1 = cosp[s*D_ + lane],      s1 = sinp[s*D_ + lane];
    float c2 = cosp[s*D_ + lane + 32], s2 = sinp[s*D_ + lane + 32];
    float o1 = n1*c1 - n2*s1;
    float o2 = n2*c2 + n1*s2;
    if (outf){
        outf[(size_t)row*D_ + lane]      = o1;
        outf[(size_t)row*D_ + lane + 32] = o2;
    }
    outh[(size_t)row*D_ + lane]      = __float2half_rn(o1 * mult);
    outh[(size_t)row*D_ + lane + 32] = __float2half_rn(o2 * mult);
}

// ---------------- Flash attention: 128-q tile, fp16 mma + ldmatrix ----------------
#define AQP 72    // half row stride (144B -> conflict-free LDSM)
#define ASP 132   // float row stride for S^T

__global__ __launch_bounds__(256) void attn2_kernel(
    const __half* __restrict__ Qh, const __half* __restrict__ Kh,
    const __half* __restrict__ Vt, __half* __restrict__ CTX)
{
    extern __shared__ char smraw[];
    __half* Qs = (__half*)smraw;             // [128][AQP]
    __half* Ks = Qs + 128*AQP;               // [2][64][AQP]
    __half* Vs = Ks + 2*64*AQP;              // [2][64][AQP]  rows=d, cols=key
    float*  Ss = (float*)(Vs + 2*64*AQP);    // [64][ASP]  S^T: [key][q]
    __half* Ph = (__half*)(Ss + 64*ASP);     // [128][AQP] P: [q][key]
    float* arow = (float*)(Ph + 128*AQP);    // [128]
    float* lrow = arow + 128;                // [128]

    const int tid = threadIdx.x, lane = tid & 31, wid = tid >> 5;
    const int wmk = (wid & 1) * 32;   // S^T: key offset
    const int wnq = (wid >> 1) * 32;  // S^T: q offset
    const int wq  = (wid & 3) * 32;   // PV: q offset
    const int wd  = (wid >> 2) * 32;  // PV: d offset
    const int l16 = lane & 15, lh = lane >> 4;
    const int g8h = lane >> 3, l8 = lane & 7;

    const int qt = blockIdx.x, bh = blockIdx.y;
    const int b = bh >> 5, h = bh & 31, g = h >> 2;

    const __half* Qbase = Qh + (((size_t)b*H_ + h)*S_ + (size_t)qt*128) * D_;
    const __half* Kbase = Kh + ((size_t)b*G_ + g) * (size_t)S_ * D_;
    const __half* Vbase = Vt + ((size_t)b*G_ + g) * (size_t)D_ * S_;

    // prologue: Q (128x64) + K/V tile 0 (64x64 each)
    {
        int r = tid >> 1, c0 = (tid & 1) * 32;
        const __half* qp = Qbase + (size_t)r*D_ + c0;
        cp16(&Qs[r*AQP + c0],      qp);
        cp16(&Qs[r*AQP + c0 + 8],  qp + 8);
        cp16(&Qs[r*AQP + c0 + 16], qp + 16);
        cp16(&Qs[r*AQP + c0 + 24], qp + 24);
        int r2 = tid >> 2, c2 = (tid & 3) * 16;
        const __half* kp = Kbase + (size_t)r2*D_ + c2;
        cp16(&Ks[r2*AQP + c2],     kp);
        cp16(&Ks[r2*AQP + c2 + 8], kp + 8);
        const __half* vp = Vbase + (size_t)r2*S_ + c2;
        cp16(&Vs[r2*AQP + c2],     vp);
        cp16(&Vs[r2*AQP + c2 + 8], vp + 8);
    }
    cp_commit();

    float m_r = -1e30f, l_r = 0.f;     // state for tid<128 (q = tid)
    float o[2][4][4];
    #pragma unroll
    for (int mi=0;mi<2;mi++)
        #pragma unroll
        for (int ni=0;ni<4;ni++)
            #pragma unroll
            for (int r=0;r<4;r++) o[mi][ni][r] = 0.f;

    const int nkt = 2*qt + 2;
    for (int kt = 0; kt < nkt; ++kt){
        const int st = kt & 1;
        if (kt + 1 < nkt){
            const int sn = st ^ 1;
            int r2 = tid >> 2, c2 = (tid & 3) * 16;
            const __half* kp = Kbase + ((size_t)(kt+1)*64 + r2)*D_ + c2;
            cp16(&Ks[(sn*64 + r2)*AQP + c2],     kp);
            cp16(&Ks[(sn*64 + r2)*AQP + c2 + 8], kp + 8);
            const __half* vp = Vbase + (size_t)r2*S_ + (size_t)(kt+1)*64 + c2;
            cp16(&Vs[(sn*64 + r2)*AQP + c2],     vp);
            cp16(&Vs[(sn*64 + r2)*AQP + c2 + 8], vp + 8);
            cp_commit();
            cp_wait<1>();
        } else {
            cp_wait<0>();
        }
        __syncthreads();

        // ---- S^T = K @ Q^T : M=key(64), N=q(128) ----
        float sc[2][4][4];
        #pragma unroll
        for (int mi=0;mi<2;mi++)
            #pragma unroll
            for (int ni=0;ni<4;ni++)
                #pragma unroll
                for (int r=0;r<4;r++) sc[mi][ni][r] = 0.f;

        #pragma unroll
        for (int ks = 0; ks < 4; ks++){
            const int kk = ks * 16;
            uint32_t a[2][4], bq[2][4];
            #pragma unroll
            for (int mi = 0; mi < 2; mi++)
                ldsm4(a[mi], &Ks[(st*64 + wmk + mi*16 + l16)*AQP + kk + lh*8]);
            #pragma unroll
            for (int ni2 = 0; ni2 < 2; ni2++)
                ldsm4(bq[ni2], &Qs[(wnq + ni2*16 + (g8h>>1)*8 + l8)*AQP + kk + (g8h&1)*8]);
            #pragma unroll
            for (int mi = 0; mi < 2; mi++)
                #pragma unroll
                for (int ni = 0; ni < 4; ni++)
                    mma16816(sc[mi][ni], a[mi], &bq[ni>>1][(ni&1)*2]);
        }

        // mask + store S^T[key][q]
        const bool domask = (kt >= 2*qt);
        const int koff = kt*64 - qt*128;    // key_global - q_tile_base
        #pragma unroll
        for (int mi = 0; mi < 2; mi++)
            #pragma unroll
            for (int ni = 0; ni < 4; ni++){
                int key = wmk + mi*16 + (lane >> 2);
                int q   = wnq + ni*8  + (lane & 3)*2;
                float v0 = sc[mi][ni][0], v1 = sc[mi][ni][1];
                float v2 = sc[mi][ni][2], v3 = sc[mi][ni][3];
                if (domask){
                    int kg = koff + key;
                    if (kg     > q    ) v0 = -1e30f;
                    if (kg     > q + 1) v1 = -1e30f;
                    if (kg + 8 > q    ) v2 = -1e30f;
                    if (kg + 8 > q + 1) v3 = -1e30f;
                }
                *(float2*)&Ss[key*ASP + q]     = make_float2(v0, v1);
                *(float2*)&Ss[(key+8)*ASP + q] = make_float2(v2, v3);
            }
        __syncthreads();

        // ---- online softmax: thread q (tid<128) owns column q ----
        if (tid < 128){
            const int q = tid;
            float mx = -1e30f;
            #pragma unroll 8
            for (int c = 0; c < 64; c++) mx = fmaxf(mx, Ss[c*ASP + q]);
            float mnew  = fmaxf(m_r, mx);
            float alpha = __expf(m_r - mnew);
            float sum = 0.f;
            #pragma unroll 4
            for (int j = 0; j < 32; j++){
                int c2 = (j + q) & 31;
                float e0 = __expf(Ss[(2*c2  )*ASP + q] - mnew);
                float e1 = __expf(Ss[(2*c2+1)*ASP + q] - mnew);
                __half h0 = __float2half_rn(e0), h1 = __float2half_rn(e1);
                sum += __half2float(h0) + __half2float(h1);
                *(__half2*)&Ph[q*AQP + 2*c2] = __halves2half2(h0, h1);
            }
            l_r = l_r * alpha + sum;
            m_r = mnew;
            arow[q] = alpha;
        }
        __syncthreads();

        // ---- rescale O, then O += P @ V^T : M=q(128), N=d(64) ----
        #pragma unroll
        for (int mi = 0; mi < 2; mi++){
            int r = wq + mi*16 + (lane >> 2);
            float a0 = arow[r], a1 = arow[r + 8];
            #pragma unroll
            for (int ni = 0; ni < 4; ni++){
                o[mi][ni][0] *= a0; o[mi][ni][1] *= a0;
                o[mi][ni][2] *= a1; o[mi][ni][3] *= a1;
            }
        }
        #pragma unroll
        for (int ks = 0; ks < 4; ks++){
            const int kk = ks * 16;
            uint32_t a[2][4], bv[2][4];
            #pragma unroll
            for (int mi = 0; mi < 2; mi++)
                ldsm4(a[mi], &Ph[(wq + mi*16 + l16)*AQP + kk + lh*8]);
            #pragma unroll
            for (int ni2 = 0; ni2 < 2; ni2++)
                ldsm4(bv[ni2], &Vs[(st*64 + wd + ni2*16 + (g8h>>1)*8 + l8)*AQP + kk + (g8h&1)*8]);
            #pragma unroll
            for (int mi = 0; mi < 2; mi++)
                #pragma unroll
                for (int ni = 0; ni < 4; ni++)
                    mma16816(o[mi][ni], a[mi], &bv[ni>>1][(ni&1)*2]);
        }
        __syncthreads();
    }

    if (tid < 128) lrow[tid] = 1.0f / l_r;
    __syncthreads();

    #pragma unroll
    for (int mi = 0; mi < 2; mi++)
        #pragma unroll
        for (int ni = 0; ni < 4; ni++){
            int q = wq + mi*16 + (lane >> 2);
            int d = wd + ni*8  + (lane & 3)*2;
            int s0 = qt*128 + q;
            float i0 = lrow[q], i1 = lrow[q + 8];
            __half2 h01 = __halves2half2(__float2half_rn(o[mi][ni][0] * i0),
                                         __float2half_rn(o[mi][ni][1] * i0));
            __half2 h23 = __halves2half2(__float2half_rn(o[mi][ni][2] * i1),
                                         __float2half_rn(o[mi][ni][3] * i1));
            *(__half2*)&CTX[(((size_t)b*S_ + s0    )*H_ + h)*D_ + d] = h01;
            *(__half2*)&CTX[(((size_t)b*S_ + s0 + 8)*H_ + h)*D_ + d] = h23;
        }
}

// ---------------- launch ----------------
extern "C" void kernel_launch(void* const* d_in, const int* in_sizes, int n_in,
                              void* d_out, int out_size)
{
    const float* x      = (const float*)d_in[0];
    const float* cosp   = (const float*)d_in[2];
    const float* sinp   = (const float*)d_in[3];
    const float* Wq     = (const float*)d_in[4];
    const float* Wk     = (const float*)d_in[5];
    const float* Wv     = (const float*)d_in[6];
    const float* Wo     = (const float*)d_in[7];
    const float* qscale = (const float*)d_in[8];
    const float* kscale = (const float*)d_in[9];

    float* out  = (float*)d_out;
    float* Kout = out + OUT_ELEMS;
    float* Vout = Kout + KV_ELEMS;

    __half *xh, *Wqt, *Wkt, *Wvt, *Wot, *Qh, *Kh, *Vt, *ctxh;
    float *Qf;
    cudaGetSymbolAddress((void**)&xh,  g_xh);
    cudaGetSymbolAddress((void**)&Wqt, g_Wqt);
    cudaGetSymbolAddress((void**)&Wkt, g_Wkt);
    cudaGetSymbolAddress((void**)&Wvt, g_Wvt);
    cudaGetSymbolAddress((void**)&Wot, g_Wot);
    cudaGetSymbolAddress((void**)&Qf,  g_Qf);
    cudaGetSymbolAddress((void**)&Qh,  g_Qh);
    cudaGetSymbolAddress((void**)&Kh,  g_Kh);
    cudaGetSymbolAddress((void**)&Vt,  g_Vt);
    cudaGetSymbolAddress((void**)&ctxh, g_ctxh);

    const int gemmSmem = 2 * 3 * GBM * GST * (int)sizeof(__half);   // 61440
    cudaFuncSetAttribute(hgemm_kernel, cudaFuncAttributeMaxDynamicSharedMemorySize, gemmSmem);

    // convert inputs
    {
        int n4 = (M_*DIN_)/4;
        f2h_kernel<<<(n4+255)/256, 256>>>(x, xh, n4);
        dim3 tb(32,8);
        wtrans_kernel<<<dim3((H_*D_)/32, DIN_/32), tb>>>(Wq, Wqt, DIN_, H_*D_);
        wtrans_kernel<<<dim3((G_*D_)/32, DIN_/32), tb>>>(Wk, Wkt, DIN_, G_*D_);
        wtrans_kernel<<<dim3((G_*D_)/32, DIN_/32), tb>>>(Wv, Wvt, DIN_, G_*D_);
        wtrans_kernel<<<dim3(DIN_/32, (H_*D_)/32), tb>>>(Wo, Wot, H_*D_, DIN_);
    }

    // projections
    hgemm_kernel<<<dim3((H_*D_)/GBN, M_/GBM), 256, gemmSmem>>>(xh, Wqt, Qf,   H_*D_, DIN_, 1, H_);
    hgemm_kernel<<<dim3((G_*D_)/GBN, M_/GBM), 256, gemmSmem>>>(xh, Wkt, Kout, G_*D_, DIN_, 1, G_);
    hgemm_kernel<<<dim3((G_*D_)/GBN, M_/GBM), 256, gemmSmem>>>(xh, Wvt, Vout, G_*D_, DIN_, 1, G_);

    // rmsnorm + rope (+half), V transpose
    rmsrope2_kernel<<<(B_*H_*S_)/8, 256>>>(Qf, nullptr, Qh, cosp, sinp, qscale, B_*H_*S_, 0.125f);
    rmsrope2_kernel<<<(B_*G_*S_)/8, 256>>>(Kout, Kout, Kh, cosp, sinp, kscale, B_*G_*S_, 1.0f);
    vtrans_kernel<<<dim3(S_/32, D_/32, B_*G_), dim3(32,8)>>>(Vout, Vt);

    // attention
    {
        int smem = (128*AQP + 2*64*AQP + 2*64*AQP + 128*AQP) * 2   // halves
                 + (64*ASP + 256) * 4;                              // floats
        cudaFuncSetAttribute(attn2_kernel, cudaFuncAttributeMaxDynamicSharedMemorySize, smem);
        attn2_kernel<<<dim3(S_/128, B_*H_), 256, smem>>>(Qh, Kh, Vt, ctxh);
    }

    // output projection
    hgemm_kernel<<<dim3(DIN_/GBN, M_/GBM), 256, gemmSmem>>>(ctxh, Wot, out, DIN_, H_*D_, 0, 0);
}

// round 5
// speedup vs baseline: 6.1271x; 1.3593x over previous
#include <cuda_runtime.h>
#include <cuda_fp16.h>
#include <cstdint>
#include <math.h>

#define B_   2
#define S_   2048
#define DIN_ 2048
#define H_   32
#define G_   8
#define D_   64
#define M_   (B_*S_)

#define OUT_ELEMS ((size_t)B_*S_*DIN_)
#define KV_ELEMS  ((size_t)B_*G_*S_*D_)

// ---------------- scratch ----------------
__device__ __half g_xh   [(size_t)M_*DIN_];
__device__ __half g_Wqkvt[(size_t)(H_*D_ + 2*G_*D_)*DIN_];  // [3072][2048]
__device__ __half g_Wot  [(size_t)DIN_*H_*D_];
__device__ float  g_Qf   [(size_t)B_*H_*S_*D_];
__device__ __half g_Qh   [(size_t)B_*H_*S_*D_];
__device__ __half g_Kh   [KV_ELEMS];
__device__ __half g_Vt   [KV_ELEMS];             // (b,g,d,s)
__device__ __half g_ctxh [(size_t)M_*H_*D_];

// ---------------- PTX helpers ----------------
__device__ __forceinline__ void cp16(void* s, const void* g){
    uint32_t sa = (uint32_t)__cvta_generic_to_shared(s);
    asm volatile("cp.async.cg.shared.global [%0], [%1], 16;\n" :: "r"(sa), "l"(g));
}
__device__ __forceinline__ void cp_commit(){ asm volatile("cp.async.commit_group;\n"); }
template<int N> __device__ __forceinline__ void cp_wait(){
    asm volatile("cp.async.wait_group %0;\n" :: "n"(N));
}
__device__ __forceinline__ void mma16816(float* c, const uint32_t* a, const uint32_t* b){
    asm volatile("mma.sync.aligned.m16n8k16.row.col.f32.f16.f16.f32 "
        "{%0,%1,%2,%3},{%4,%5,%6,%7},{%8,%9},{%0,%1,%2,%3};\n"
        : "+f"(c[0]),"+f"(c[1]),"+f"(c[2]),"+f"(c[3])
        : "r"(a[0]),"r"(a[1]),"r"(a[2]),"r"(a[3]),"r"(b[0]),"r"(b[1]));
}
__device__ __forceinline__ void ldsm4(uint32_t* r, const __half* p){
    uint32_t a = (uint32_t)__cvta_generic_to_shared(p);
    asm volatile("ldmatrix.sync.aligned.m8n8.x4.shared.b16 {%0,%1,%2,%3}, [%4];"
        : "=r"(r[0]),"=r"(r[1]),"=r"(r[2]),"=r"(r[3]) : "r"(a));
}
__device__ __forceinline__ uint32_t h2pack(float a, float b){
    __half2 h = __halves2half2(__float2half_rn(a), __float2half_rn(b));
    return *(uint32_t*)&h;
}

// ---------------- conversion kernels ----------------
__global__ void f2h_kernel(const float* __restrict__ in, __half* __restrict__ out, int n4){
    int i = blockIdx.x * blockDim.x + threadIdx.x;
    if (i >= n4) return;
    float4 v = *(const float4*)(in + (size_t)i*4);
    __half* o = out + (size_t)i*4;
    o[0]=__float2half_rn(v.x); o[1]=__float2half_rn(v.y);
    o[2]=__float2half_rn(v.z); o[3]=__float2half_rn(v.w);
}

__global__ void wtrans_kernel(const float* __restrict__ W, __half* __restrict__ Wt, int K, int N){
    __shared__ float t[32][33];
    int n0 = blockIdx.x*32, k0 = blockIdx.y*32;
    for (int j = threadIdx.y; j < 32; j += 8)
        t[j][threadIdx.x] = W[(size_t)(k0+j)*N + n0 + threadIdx.x];
    __syncthreads();
    for (int j = threadIdx.y; j < 32; j += 8)
        Wt[(size_t)(n0+j)*K + k0 + threadIdx.x] = __float2half_rn(t[threadIdx.x][j]);
}

__global__ void vtrans_kernel(const float* __restrict__ V, __half* __restrict__ Vt){
    __shared__ float t[32][33];
    int s0 = blockIdx.x*32, d0 = blockIdx.y*32, bg = blockIdx.z;
    const float* Vb = V + (size_t)bg*S_*D_;
    __half* Vo = Vt + (size_t)bg*S_*D_;
    for (int j = threadIdx.y; j < 32; j += 8)
        t[j][threadIdx.x] = Vb[(size_t)(s0+j)*D_ + d0 + threadIdx.x];
    __syncthreads();
    for (int j = threadIdx.y; j < 32; j += 8)
        Vo[(size_t)(d0+j)*S_ + s0 + threadIdx.x] = __float2half_rn(t[threadIdx.x][j]);
}

// ---------------- HGEMM: 3-stage cp.async + ldmatrix ----------------
#define GBM 128
#define GBN 128
#define GBK 32
#define GST 40

// mode 0: plain row-major C
// mode 2: fused QKV: bn<2048 -> Q headed(32); bn<2560 -> Ck headed(8); else Cv headed(8)
__global__ __launch_bounds__(256,2) void hgemm_kernel(
    const __half* __restrict__ A, const __half* __restrict__ Bt,
    float* __restrict__ C, float* __restrict__ Ck, float* __restrict__ Cv,
    int Ndim, int Kdim, int mode)
{
    extern __shared__ __half hs[];
    __half* As = hs;
    __half* Bs = hs + 3*GBM*GST;

    const int tid = threadIdx.x, lane = tid & 31, wid = tid >> 5;
    const int wm = (wid & 1) * 64, wn = (wid >> 1) * 32;
    const int bm = blockIdx.y * GBM, bn = blockIdx.x * GBN;

    const int ldRow = tid >> 1;
    const int ldOff = (tid & 1) * 16;
    const __half* Ap = A  + (size_t)(bm + ldRow) * Kdim + ldOff;
    const __half* Bp = Bt + (size_t)(bn + ldRow) * Kdim + ldOff;

    const int l16 = lane & 15, lh = lane >> 4;
    const int g8h = lane >> 3, l8 = lane & 7;

    float acc[4][4][4];
    #pragma unroll
    for (int mi=0; mi<4; mi++)
        #pragma unroll
        for (int ni=0; ni<4; ni++)
            #pragma unroll
            for (int r=0; r<4; r++) acc[mi][ni][r] = 0.f;

    const int nk = Kdim / GBK;
    #pragma unroll
    for (int s = 0; s < 2; s++){
        int k0 = s * GBK;
        cp16(&As[(s*GBM + ldRow)*GST + ldOff],     Ap + k0);
        cp16(&As[(s*GBM + ldRow)*GST + ldOff + 8], Ap + k0 + 8);
        cp16(&Bs[(s*GBN + ldRow)*GST + ldOff],     Bp + k0);
        cp16(&Bs[(s*GBN + ldRow)*GST + ldOff + 8], Bp + k0 + 8);
        cp_commit();
    }

    for (int it = 0; it < nk; ++it){
        const int st = it % 3;
        if (it + 1 < nk) cp_wait<1>(); else cp_wait<0>();
        __syncthreads();
        if (it + 2 < nk){
            int sn = (it + 2) % 3;
            int k0 = (it + 2) * GBK;
            cp16(&As[(sn*GBM + ldRow)*GST + ldOff],     Ap + k0);
            cp16(&As[(sn*GBM + ldRow)*GST + ldOff + 8], Ap + k0 + 8);
            cp16(&Bs[(sn*GBN + ldRow)*GST + ldOff],     Bp + k0);
            cp16(&Bs[(sn*GBN + ldRow)*GST + ldOff + 8], Bp + k0 + 8);
            cp_commit();
        }

        #pragma unroll
        for (int ks = 0; ks < 2; ks++){
            const int kk = ks * 16;
            uint32_t a[4][4], bq[2][4];
            #pragma unroll
            for (int mi = 0; mi < 4; mi++)
                ldsm4(a[mi], &As[(st*GBM + wm + mi*16 + l16)*GST + kk + lh*8]);
            #pragma unroll
            for (int ni2 = 0; ni2 < 2; ni2++)
                ldsm4(bq[ni2], &Bs[(st*GBN + wn + ni2*16 + (g8h>>1)*8 + l8)*GST + kk + (g8h&1)*8]);
            #pragma unroll
            for (int mi = 0; mi < 4; mi++)
                #pragma unroll
                for (int ni = 0; ni < 4; ni++)
                    mma16816(acc[mi][ni], a[mi], &bq[ni>>1][(ni&1)*2]);
        }
        __syncthreads();
    }

    if (mode == 0){
        #pragma unroll
        for (int mi = 0; mi < 4; mi++)
            #pragma unroll
            for (int ni = 0; ni < 4; ni++){
                int r = bm + wm + mi*16 + (lane >> 2);
                int c = bn + wn + ni*8 + (lane & 3)*2;
                *(float2*)&C[(size_t)r*Ndim + c]     = make_float2(acc[mi][ni][0], acc[mi][ni][1]);
                *(float2*)&C[(size_t)(r+8)*Ndim + c] = make_float2(acc[mi][ni][2], acc[mi][ni][3]);
            }
    } else {
        float* T; int nb, Hn;
        if (bn < 2048)      { T = C;  nb = 0;    Hn = 32; }
        else if (bn < 2560) { T = Ck; nb = 2048; Hn = 8;  }
        else                { T = Cv; nb = 2560; Hn = 8;  }
        #pragma unroll
        for (int mi = 0; mi < 4; mi++)
            #pragma unroll
            for (int ni = 0; ni < 4; ni++){
                int r = bm + wm + mi*16 + (lane >> 2);
                int c = bn + wn + ni*8 + (lane & 3)*2 - nb;
                int bb = r >> 11;
                int hh = c >> 6, dd = c & 63;
                size_t base = (((size_t)bb*Hn + hh)*S_ + (r & (S_-1)))*D_ + dd;
                *(float2*)&T[base] = make_float2(acc[mi][ni][0], acc[mi][ni][1]);
                size_t base2 = (((size_t)bb*Hn + hh)*S_ + ((r+8) & (S_-1)))*D_ + dd;
                *(float2*)&T[base2] = make_float2(acc[mi][ni][2], acc[mi][ni][3]);
            }
    }
}

// ---------------- fused RMSNorm + RoPE ----------------
__global__ void rmsrope2_kernel(const float* __restrict__ in, float* __restrict__ outf,
                                __half* __restrict__ outh,
                                const float* __restrict__ cosp, const float* __restrict__ sinp,
                                const float* __restrict__ scale, int totalRows, float mult)
{
    int row  = blockIdx.x * (blockDim.x >> 5) + (threadIdx.x >> 5);
    int lane = threadIdx.x & 31;
    if (row >= totalRows) return;
    int s = row & (S_ - 1);
    const float* p = in + (size_t)row * D_;
    float v1 = p[lane], v2 = p[lane + 32];
    float ss = v1*v1 + v2*v2;
    #pragma unroll
    for (int o = 16; o > 0; o >>= 1) ss += __shfl_xor_sync(0xffffffffu, ss, o);
    float inv = rsqrtf(ss * (1.0f/64.0f) + 1e-6f);
    float n1 = v1 * inv * scale[lane];
    float n2 = v2 * inv * scale[lane + 32];
    float c1 = cosp[s*D_ + lane],      s1 = sinp[s*D_ + lane];
    float c2 = cosp[s*D_ + lane + 32], s2 = sinp[s*D_ + lane + 32];
    float o1 = n1*c1 - n2*s1;
    float o2 = n2*c2 + n1*s2;
    if (outf){
        outf[(size_t)row*D_ + lane]      = o1;
        outf[(size_t)row*D_ + lane + 32] = o2;
    }
    outh[(size_t)row*D_ + lane]      = __float2half_rn(o1 * mult);
    outh[(size_t)row*D_ + lane + 32] = __float2half_rn(o2 * mult);
}

// ---------------- FA2 attention: register softmax, 128q x 64k ----------------
#define AQP 72

__global__ __launch_bounds__(256) void attn3_kernel(
    const __half* __restrict__ Qh, const __half* __restrict__ Kh,
    const __half* __restrict__ Vt, __half* __restrict__ CTX)
{
    extern __shared__ char smraw[];
    __half* Qs = (__half*)smraw;            // [128][AQP]
    __half* Ks = Qs + 128*AQP;              // [3][64][AQP]   rows=key, cols=d
    __half* Vs = Ks + 3*64*AQP;             // [3][64][AQP]   rows=d,   cols=key

    const int tid = threadIdx.x, lane = tid & 31, w = tid >> 5;
    const int l16 = lane & 15, lh = lane >> 4;
    const int g8h = lane >> 3, l8 = lane & 7;

    const int qt = blockIdx.x, bh = blockIdx.y;
    const int b = bh >> 5, h = bh & 31, g = h >> 2;

    const __half* Qbase = Qh + (((size_t)b*H_ + h)*S_ + (size_t)qt*128) * D_;
    const __half* Kbase = Kh + ((size_t)b*G_ + g) * (size_t)S_ * D_;
    const __half* Vbase = Vt + ((size_t)b*G_ + g) * (size_t)D_ * S_;

    const int nkt = 2*qt + 2;

    // prologue: Q (own group), then K/V tiles 0 and 1
    {
        int r = tid >> 1, c0 = (tid & 1) * 32;
        const __half* qp = Qbase + (size_t)r*D_ + c0;
        cp16(&Qs[r*AQP + c0],      qp);
        cp16(&Qs[r*AQP + c0 + 8],  qp + 8);
        cp16(&Qs[r*AQP + c0 + 16], qp + 16);
        cp16(&Qs[r*AQP + c0 + 24], qp + 24);
        cp_commit();
        int r2 = tid >> 2, c2 = (tid & 3) * 16;
        #pragma unroll
        for (int t = 0; t < 2; t++){
            const __half* kp = Kbase + ((size_t)t*64 + r2)*D_ + c2;
            cp16(&Ks[(t*64 + r2)*AQP + c2],     kp);
            cp16(&Ks[(t*64 + r2)*AQP + c2 + 8], kp + 8);
            const __half* vp = Vbase + (size_t)r2*S_ + (size_t)t*64 + c2;
            cp16(&Vs[(t*64 + r2)*AQP + c2],     vp);
            cp16(&Vs[(t*64 + r2)*AQP + c2 + 8], vp + 8);
            cp_commit();
        }
    }
    cp_wait<2>();
    __syncthreads();

    // preload Q fragments (Qs not touched afterwards)
    uint32_t qa[4][4];
    #pragma unroll
    for (int ks = 0; ks < 4; ks++)
        ldsm4(qa[ks], &Qs[(w*16 + l16)*AQP + ks*16 + lh*8]);

    float o[8][4];
    #pragma unroll
    for (int j = 0; j < 8; j++)
        #pragma unroll
        for (int r = 0; r < 4; r++) o[j][r] = 0.f;
    float m0 = -1e30f, m1 = -1e30f, l0 = 0.f, l1 = 0.f;

    const int qmin = qt*128 + w*16;
    const int r2 = tid >> 2, c2l = (tid & 3) * 16;

    for (int kt = 0; kt < nkt; ++kt){
        const int st = kt % 3;
        if (kt + 1 < nkt) cp_wait<1>(); else cp_wait<0>();
        __syncthreads();
        if (kt + 2 < nkt){
            int sn = (kt + 2) % 3;
            const __half* kp = Kbase + ((size_t)(kt+2)*64 + r2)*D_ + c2l;
            cp16(&Ks[(sn*64 + r2)*AQP + c2l],     kp);
            cp16(&Ks[(sn*64 + r2)*AQP + c2l + 8], kp + 8);
            const __half* vp = Vbase + (size_t)r2*S_ + (size_t)(kt+2)*64 + c2l;
            cp16(&Vs[(sn*64 + r2)*AQP + c2l],     vp);
            cp16(&Vs[(sn*64 + r2)*AQP + c2l + 8], vp + 8);
            cp_commit();
        }

        if (kt*64 <= qmin + 15){   // not fully masked for this warp
            // ---- S = Q @ K^T  (M=16 q, N=64 key) ----
            float sc[8][4];
            #pragma unroll
            for (int j = 0; j < 8; j++)
                #pragma unroll
                for (int r = 0; r < 4; r++) sc[j][r] = 0.f;

            #pragma unroll
            for (int ks = 0; ks < 4; ks++){
                uint32_t bq[4][4];
                #pragma unroll
                for (int nt2 = 0; nt2 < 4; nt2++)
                    ldsm4(bq[nt2], &Ks[(st*64 + nt2*16 + (g8h>>1)*8 + l8)*AQP + ks*16 + (g8h&1)*8]);
                #pragma unroll
                for (int j = 0; j < 8; j++)
                    mma16816(sc[j], qa[ks], &bq[j>>1][(j&1)*2]);
            }

            // ---- mask ----
            const int qg0 = qmin + (lane >> 2);
            if (kt*64 + 63 > qmin){
                #pragma unroll
                for (int j = 0; j < 8; j++){
                    int kg = kt*64 + j*8 + (lane & 3)*2;
                    if (kg     > qg0    ) sc[j][0] = -1e30f;
                    if (kg + 1 > qg0    ) sc[j][1] = -1e30f;
                    if (kg     > qg0 + 8) sc[j][2] = -1e30f;
                    if (kg + 1 > qg0 + 8) sc[j][3] = -1e30f;
                }
            }

            // ---- register softmax (rows r0=lane>>2, r1=r0+8) ----
            float mx0 = -1e30f, mx1 = -1e30f;
            #pragma unroll
            for (int j = 0; j < 8; j++){
                mx0 = fmaxf(mx0, fmaxf(sc[j][0], sc[j][1]));
                mx1 = fmaxf(mx1, fmaxf(sc[j][2], sc[j][3]));
            }
            mx0 = fmaxf(mx0, __shfl_xor_sync(0xffffffffu, mx0, 1));
            mx0 = fmaxf(mx0, __shfl_xor_sync(0xffffffffu, mx0, 2));
            mx1 = fmaxf(mx1, __shfl_xor_sync(0xffffffffu, mx1, 1));
            mx1 = fmaxf(mx1, __shfl_xor_sync(0xffffffffu, mx1, 2));
            float mn0 = fmaxf(m0, mx0), mn1 = fmaxf(m1, mx1);
            float al0 = __expf(m0 - mn0), al1 = __expf(m1 - mn1);
            m0 = mn0; m1 = mn1;

            float s0 = 0.f, s1 = 0.f;
            uint32_t pa[4][4];
            #pragma unroll
            for (int j = 0; j < 8; j++){
                float e0 = __expf(sc[j][0] - mn0);
                float e1 = __expf(sc[j][1] - mn0);
                float e2 = __expf(sc[j][2] - mn1);
                float e3 = __expf(sc[j][3] - mn1);
                s0 += e0 + e1;  s1 += e2 + e3;
                int ks = j >> 1, hi = (j & 1) * 2;
                pa[ks][hi]     = h2pack(e0, e1);
                pa[ks][hi + 1] = h2pack(e2, e3);
            }
            s0 += __shfl_xor_sync(0xffffffffu, s0, 1);
            s0 += __shfl_xor_sync(0xffffffffu, s0, 2);
            s1 += __shfl_xor_sync(0xffffffffu, s1, 1);
            s1 += __shfl_xor_sync(0xffffffffu, s1, 2);
            l0 = l0 * al0 + s0;
            l1 = l1 * al1 + s1;

            #pragma unroll
            for (int j = 0; j < 8; j++){
                o[j][0] *= al0; o[j][1] *= al0;
                o[j][2] *= al1; o[j][3] *= al1;
            }

            // ---- O += P @ V  (N=64 d, K=key; B = Vt[d][key]) ----
            #pragma unroll
            for (int ks = 0; ks < 4; ks++){
                uint32_t bv[4][4];
                #pragma unroll
                for (int nt2 = 0; nt2 < 4; nt2++)
                    ldsm4(bv[nt2], &Vs[(st*64 + nt2*16 + (g8h>>1)*8 + l8)*AQP + ks*16 + (g8h&1)*8]);
                #pragma unroll
                for (int j = 0; j < 8; j++)
                    mma16816(o[j], pa[ks], &bv[j>>1][(j&1)*2]);
            }
        }
    }

    float i0 = 1.0f / l0, i1 = 1.0f / l1;
    const int q0 = w*16 + (lane >> 2);
    const int sg0 = qt*128 + q0;
    #pragma unroll
    for (int j = 0; j < 8; j++){
        int d = j*8 + (lane & 3)*2;
        __half2 hA = __halves2half2(__float2half_rn(o[j][0]*i0), __float2half_rn(o[j][1]*i0));
        __half2 hB = __halves2half2(__float2half_rn(o[j][2]*i1), __float2half_rn(o[j][3]*i1));
        *(__half2*)&CTX[(((size_t)b*S_ + sg0    )*H_ + h)*D_ + d] = hA;
        *(__half2*)&CTX[(((size_t)b*S_ + sg0 + 8)*H_ + h)*D_ + d] = hB;
    }
}

// ---------------- launch ----------------
extern "C" void kernel_launch(void* const* d_in, const int* in_sizes, int n_in,
                              void* d_out, int out_size)
{
    const float* x      = (const float*)d_in[0];
    const float* cosp   = (const float*)d_in[2];
    const float* sinp   = (const float*)d_in[3];
    const float* Wq     = (const float*)d_in[4];
    const float* Wk     = (const float*)d_in[5];
    const float* Wv     = (const float*)d_in[6];
    const float* Wo     = (const float*)d_in[7];
    const float* qscale = (const float*)d_in[8];
    const float* kscale = (const float*)d_in[9];

    float* out  = (float*)d_out;
    float* Kout = out + OUT_ELEMS;
    float* Vout = Kout + KV_ELEMS;

    __half *xh, *Wqkvt, *Wot, *Qh, *Kh, *Vt, *ctxh;
    float *Qf;
    cudaGetSymbolAddress((void**)&xh,    g_xh);
    cudaGetSymbolAddress((void**)&Wqkvt, g_Wqkvt);
    cudaGetSymbolAddress((void**)&Wot,   g_Wot);
    cudaGetSymbolAddress((void**)&Qf,    g_Qf);
    cudaGetSymbolAddress((void**)&Qh,    g_Qh);
    cudaGetSymbolAddress((void**)&Kh,    g_Kh);
    cudaGetSymbolAddress((void**)&Vt,    g_Vt);
    cudaGetSymbolAddress((void**)&ctxh,  g_ctxh);

    const int gemmSmem = 2 * 3 * GBM * GST * (int)sizeof(__half);
    cudaFuncSetAttribute(hgemm_kernel, cudaFuncAttributeMaxDynamicSharedMemorySize, gemmSmem);

    // convert inputs; concat W^T = [Wq^T ; Wk^T ; Wv^T] rows
    {
        int n4 = (M_*DIN_)/4;
        f2h_kernel<<<(n4+255)/256, 256>>>(x, xh, n4);
        dim3 tb(32,8);
        wtrans_kernel<<<dim3((H_*D_)/32, DIN_/32), tb>>>(Wq, Wqkvt,                         DIN_, H_*D_);
        wtrans_kernel<<<dim3((G_*D_)/32, DIN_/32), tb>>>(Wk, Wqkvt + (size_t)2048*DIN_,     DIN_, G_*D_);
        wtrans_kernel<<<dim3((G_*D_)/32, DIN_/32), tb>>>(Wv, Wqkvt + (size_t)2560*DIN_,     DIN_, G_*D_);
        wtrans_kernel<<<dim3(DIN_/32, (H_*D_)/32), tb>>>(Wo, Wot, H_*D_, DIN_);
    }

    // fused QKV projection: N = 3072
    hgemm_kernel<<<dim3(3072/GBN, M_/GBM), 256, gemmSmem>>>(xh, Wqkvt, Qf, Kout, Vout, 3072, DIN_, 2);

    // rmsnorm + rope (+half), V transpose
    rmsrope2_kernel<<<(B_*H_*S_)/8, 256>>>(Qf, nullptr, Qh, cosp, sinp, qscale, B_*H_*S_, 0.125f);
    rmsrope2_kernel<<<(B_*G_*S_)/8, 256>>>(Kout, Kout, Kh, cosp, sinp, kscale, B_*G_*S_, 1.0f);
    vtrans_kernel<<<dim3(S_/32, D_/32, B_*G_), dim3(32,8)>>>(Vout, Vt);

    // attention
    {
        int smem = (128*AQP + 3*64*AQP + 3*64*AQP) * (int)sizeof(__half);
        cudaFuncSetAttribute(attn3_kernel, cudaFuncAttributeMaxDynamicSharedMemorySize, smem);
        attn3_kernel<<<dim3(S_/128, B_*H_), 256, smem>>>(Qh, Kh, Vt, ctxh);
    }

    // output projection
    hgemm_kernel<<<dim3(DIN_/GBN, M_/GBM), 256, gemmSmem>>>(ctxh, Wot, out, nullptr, nullptr, DIN_, H_*D_, 0);
}